// round 16
// baseline (speedup 1.0000x reference)
#include <cuda_runtime.h>
#include <cuda_bf16.h>
#include <cstdint>

constexpr int HID = 128;
constexpr int N_NODES_MAX = 100000;
constexpr int N_EDGES_MAX = 1600000;
constexpr int N_EDGE_TYPES = 8;

// Scratch (device globals: allocation-free)
__device__ float g_h[(size_t)N_NODES_MAX * HID];
__device__ float g_agg[(size_t)N_NODES_MAX * HID];
__device__ __nv_bfloat16 g_wimg[7 * 2 * 16384];
// CSR scratch
__device__ int g_deg[N_NODES_MAX];          // histogram
__device__ int g_off[N_NODES_MAX + 1];
__device__ int g_bsum[256];
__device__ int g_rank[N_EDGES_MAX];         // per-edge rank among same-dst edges
__device__ int g_packed[N_EDGES_MAX];       // src | (etype << 20)

// Side stream + fork/join events (host-side resources, static init)
struct SideStream {
    cudaStream_t s;
    cudaEvent_t fork, join;
    SideStream() {
        cudaStreamCreateWithFlags(&s, cudaStreamNonBlocking);
        cudaEventCreateWithFlags(&fork, cudaEventDisableTiming);
        cudaEventCreateWithFlags(&join, cudaEventDisableTiming);
    }
};
static SideStream g_ss;

// ---------------------------------------------------------------------------
// helpers
// ---------------------------------------------------------------------------
__device__ __forceinline__ uint32_t smem_u32(const void* p) {
    uint32_t a;
    asm("{ .reg .u64 t; cvta.to.shared.u64 t, %1; cvt.u32.u64 %0, t; }" : "=r"(a) : "l"(p));
    return a;
}
__device__ __forceinline__ void cp_async16(uint32_t saddr, const void* g) {
    asm volatile("cp.async.cg.shared.global [%0], [%1], 16;" :: "r"(saddr), "l"(g) : "memory");
}
__device__ __forceinline__ void cp_commit() {
    asm volatile("cp.async.commit_group;" ::: "memory");
}
template<int N>
__device__ __forceinline__ void cp_wait() {
    asm volatile("cp.async.wait_group %0;" :: "n"(N) : "memory");
}
__device__ __forceinline__ void mma_bf16(float* c, const uint4& a,
                                         uint32_t b0, uint32_t b1) {
    asm volatile(
        "mma.sync.aligned.m16n8k16.row.col.f32.bf16.bf16.f32 "
        "{%0,%1,%2,%3}, {%4,%5,%6,%7}, {%8,%9}, {%0,%1,%2,%3};"
        : "+f"(c[0]), "+f"(c[1]), "+f"(c[2]), "+f"(c[3])
        : "r"(a.x), "r"(a.y), "r"(a.z), "r"(a.w), "r"(b0), "r"(b1));
}
__device__ __forceinline__ void pack_hilo(float a, float b, uint32_t& hi, uint32_t& lo) {
    __nv_bfloat16 ha = __float2bfloat16_rn(a), hb = __float2bfloat16_rn(b);
    __nv_bfloat162 H(ha, hb);
    __nv_bfloat162 L(__float2bfloat16_rn(a - __bfloat162float(ha)),
                     __float2bfloat16_rn(b - __bfloat162float(hb)));
    hi = *(uint32_t*)&H;
    lo = *(uint32_t*)&L;
}

// smem layout (GEMM kernels): bias | A hi | A lo | B ring (4 x 8KB)
constexpr int OFF_BIAS = 0;                  // 2048 B
constexpr int OFF_AHI  = 2048;               // 32 KB
constexpr int OFF_ALO  = OFF_AHI + 32768;    // 32 KB
constexpr int OFF_B    = OFF_ALO + 32768;    // 4 x 8192
constexpr int SM_TOTAL = OFF_B + 4 * 8192;   // 100352 B -> 2 CTAs/SM

// frag address for element (row, k0) of the 128x128 A tile (k0 multiple of 4)
__device__ __forceinline__ uint32_t afrag_addr(int row, int k0) {
    int s    = k0 >> 4;
    int half = (k0 >> 3) & 1;
    int t    = (k0 >> 1) & 3;
    int g    = row & 7;
    int rbit = (row >> 3) & 1;
    int mt   = row >> 4;
    int r    = rbit + 2 * half;
    return (uint32_t)((s * 8 + mt) * 512 + (g * 4 + t) * 16 + r * 4);
}
__device__ __forceinline__ void write_afrag(char* smem, int row, int k0, float4 v) {
    uint32_t h01, l01, h23, l23;
    pack_hilo(v.x, v.y, h01, l01);
    pack_hilo(v.z, v.w, h23, l23);
    uint32_t base = afrag_addr(row, k0);
    *(uint32_t*)(smem + OFF_AHI + base)      = h01;
    *(uint32_t*)(smem + OFF_AHI + base + 16) = h23;
    *(uint32_t*)(smem + OFF_ALO + base)      = l01;
    *(uint32_t*)(smem + OFF_ALO + base + 16) = l23;
}

// issue one 8KB B slice (hi 4KB + lo 4KB) for k-step j into ring slot j&3
__device__ __forceinline__ void load_B_slice(char* smem, const __nv_bfloat16* wimg,
                                             int j, int tid) {
    uint32_t dst = smem_u32(smem + OFF_B + (j & 3) * 8192);
    const uint4* hs = (const uint4*)wimg + j * 256;
    const uint4* ls = (const uint4*)(wimg + 16384) + j * 256;
    cp_async16(dst + tid * 16,        hs + tid);
    cp_async16(dst + 4096 + tid * 16, ls + tid);
    cp_commit();
}

// ---------------------------------------------------------------------------
// Prep weights: split fp32 W into bf16 hi/lo in MMA B-fragment order
// ---------------------------------------------------------------------------
__global__ void prep_all_kernel(const float* W0, const float* W1, const float* W2,
                                const float* W3, const float* W4, const float* W5,
                                const float* W6, __nv_bfloat16* img) {
    const float* Ws[7] = {W0, W1, W2, W3, W4, W5, W6};
    int wi  = blockIdx.y;
    int idx = blockIdx.x * blockDim.x + threadIdx.x;
    if (idx >= 16384) return;
    int k = idx >> 7;
    int n = idx & 127;
    float w = Ws[wi][k * 128 + n];
    __nv_bfloat16 h = __float2bfloat16_rn(w);
    __nv_bfloat16 l = __float2bfloat16_rn(w - __bfloat162float(h));

    int s = k >> 4, half = (k & 15) >> 3, t = (k >> 1) & 3, e = k & 1;
    int g = n & 7, lane = g * 4 + t;
    int jt = n >> 3, jp = jt >> 1, which = jt & 1, reg = which * 2 + half;
    uint32_t off = (uint32_t)((s * 8 + jp) * 512 + lane * 16 + reg * 4 + e * 2);
    char* hi = (char*)(img + (size_t)wi * 32768);
    char* lo = hi + 32768;
    *(__nv_bfloat16*)(hi + off) = h;
    *(__nv_bfloat16*)(lo + off) = l;
}

// ---------------------------------------------------------------------------
// CSR build kernels: hist also emits per-edge rank -> fill is atomic-free
// ---------------------------------------------------------------------------
__global__ void hist_kernel(const int* __restrict__ ei, int* __restrict__ deg,
                            int* __restrict__ rank, int E) {
    int e = blockIdx.x * blockDim.x + threadIdx.x;
    if (e >= E) return;
    rank[e] = atomicAdd(&deg[ei[E + e]], 1);
}
__global__ __launch_bounds__(512) void scan1_kernel(
    const int* __restrict__ deg, int* __restrict__ out, int* __restrict__ bsum, int M)
{
    __shared__ int warp_sums[16];
    int tid = threadIdx.x;
    int base = blockIdx.x * 2048 + tid * 4;
    int v[4];
    #pragma unroll
    for (int j = 0; j < 4; j++) v[j] = (base + j < M) ? deg[base + j] : 0;
    int t = v[0] + v[1] + v[2] + v[3];
    int lane = tid & 31, wid = tid >> 5;
    int x = t;
    #pragma unroll
    for (int o = 1; o < 32; o <<= 1) {
        int y = __shfl_up_sync(0xFFFFFFFFu, x, o);
        if (lane >= o) x += y;
    }
    if (lane == 31) warp_sums[wid] = x;
    __syncthreads();
    if (wid == 0 && lane < 16) {
        int s = warp_sums[lane];
        #pragma unroll
        for (int o = 1; o < 16; o <<= 1) {
            int y = __shfl_up_sync(0xFFFFu, s, o);
            if (lane >= o) s += y;
        }
        warp_sums[lane] = s;
    }
    __syncthreads();
    int warp_excl = (wid == 0) ? 0 : warp_sums[wid - 1];
    int run = warp_excl + (x - t);
    #pragma unroll
    for (int j = 0; j < 4; j++) {
        if (base + j < M) out[base + j] = run;
        run += v[j];
    }
    if (tid == 0) bsum[blockIdx.x] = warp_sums[15];
}
// add bsum prefix: parallel warp load + shuffle reduce (nb <= 64)
__global__ __launch_bounds__(512) void scan3_kernel(
    int* __restrict__ off, const int* __restrict__ bsum, int M, int E)
{
    __shared__ int s_add;
    int tid = threadIdx.x;
    if (tid < 32) {
        int s = 0;
        int bid = (int)blockIdx.x;
        if (tid < bid)      s += bsum[tid];
        if (tid + 32 < bid) s += bsum[tid + 32];
        #pragma unroll
        for (int o = 16; o > 0; o >>= 1)
            s += __shfl_xor_sync(0xFFFFFFFFu, s, o);
        if (tid == 0) s_add = s;
    }
    __syncthreads();
    int base = blockIdx.x * 2048 + tid * 4;
    int add = s_add;
    #pragma unroll
    for (int j = 0; j < 4; j++) {
        if (base + j < M) off[base + j] += add;
    }
    if (blockIdx.x == 0 && tid == 0) off[M] = E;
}
// atomic-free fill: slot = off[dst] + rank[e]
__global__ void fill_kernel(const int* __restrict__ ei, const int* __restrict__ et,
                            const int* __restrict__ off, const int* __restrict__ rank,
                            int* __restrict__ packed, int E)
{
    int e = blockIdx.x * blockDim.x + threadIdx.x;
    if (e >= E) return;
    int d = ei[E + e];
    packed[off[d] + rank[e]] = ei[e] | (et[e] << 20);
}

// ---------------------------------------------------------------------------
// CSR aggregation (fp32): agg[n] = sum relu(h[src] + emb[et]); 8-edge unroll
// ---------------------------------------------------------------------------
__global__ __launch_bounds__(256) void agg_kernel(
    const float* __restrict__ h, const int* __restrict__ packed,
    const int* __restrict__ off, const float* __restrict__ emb,
    float* __restrict__ agg, int M)
{
    __shared__ float semb[N_EDGE_TYPES * HID];
    for (int i = threadIdx.x; i < N_EDGE_TYPES * HID; i += 256) semb[i] = emb[i];
    __syncthreads();

    int n = blockIdx.x * 8 + (threadIdx.x >> 5);
    if (n >= M) return;
    int lane = threadIdx.x & 31;
    const int k0 = lane * 4;

    int beg = off[n], end = off[n + 1];
    float4 acc = make_float4(0.f, 0.f, 0.f, 0.f);
    int e = beg;
    for (; e + 8 <= end; e += 8) {
        int p[8];
        #pragma unroll
        for (int u = 0; u < 8; u++) p[u] = __ldg(packed + e + u);
        float4 hv[8];
        #pragma unroll
        for (int u = 0; u < 8; u++)
            hv[u] = *(const float4*)(h + (size_t)(p[u] & 0xFFFFF) * HID + k0);
        #pragma unroll
        for (int u = 0; u < 8; u++) {
            const float4 ev = *(const float4*)(semb + (p[u] >> 20) * HID + k0);
            acc.x += fmaxf(hv[u].x + ev.x, 0.f);
            acc.y += fmaxf(hv[u].y + ev.y, 0.f);
            acc.z += fmaxf(hv[u].z + ev.z, 0.f);
            acc.w += fmaxf(hv[u].w + ev.w, 0.f);
        }
    }
    for (; e < end; e++) {
        int p0 = __ldg(packed + e);
        float4 h0 = *(const float4*)(h + (size_t)(p0 & 0xFFFFF) * HID + k0);
        const float4 e0 = *(const float4*)(semb + (p0 >> 20) * HID + k0);
        acc.x += fmaxf(h0.x + e0.x, 0.f);
        acc.y += fmaxf(h0.y + e0.y, 0.f);
        acc.z += fmaxf(h0.z + e0.z, 0.f);
        acc.w += fmaxf(h0.w + e0.w, 0.f);
    }
    *(float4*)(agg + (size_t)n * HID + k0) = acc;
}

// ---------------------------------------------------------------------------
// Pipelined GEMM mainloop: B slices streamed via 4-slot cp.async ring.
// PRECONDITION: slices 0,1,2 of wimg already issued by all threads.
// ---------------------------------------------------------------------------
__device__ __forceinline__ void mma_pipe(char* smem, const __nv_bfloat16* wimg,
                                         int tid, int w, int lid,
                                         float acc[2][8][4]) {
    const int mt0 = (w & 3) * 2;
    const int jp0 = (w >> 2) * 4;
    const uint4* sAh = (const uint4*)(smem + OFF_AHI);
    const uint4* sAl = (const uint4*)(smem + OFF_ALO);
    #pragma unroll
    for (int s = 0; s < 8; s++) {
        if (s < 6)      cp_wait<2>();
        else if (s == 6) cp_wait<1>();
        else            cp_wait<0>();
        __syncthreads();
        if (s + 3 < 8) load_B_slice(smem, wimg, s + 3, tid);

        const uint4* sBh = (const uint4*)(smem + OFF_B + (s & 3) * 8192);
        const uint4* sBl = (const uint4*)(smem + OFF_B + (s & 3) * 8192 + 4096);

        uint4 ah0 = sAh[(s * 8 + mt0) * 32 + lid];
        uint4 ah1 = sAh[(s * 8 + mt0 + 1) * 32 + lid];
        uint4 al0 = sAl[(s * 8 + mt0) * 32 + lid];
        uint4 al1 = sAl[(s * 8 + mt0 + 1) * 32 + lid];
        uint4 b[4];
        #pragma unroll
        for (int p = 0; p < 4; p++) b[p] = sBh[(jp0 + p) * 32 + lid];
        #pragma unroll
        for (int p = 0; p < 4; p++) {
            mma_bf16(acc[0][2 * p],     ah0, b[p].x, b[p].y);
            mma_bf16(acc[1][2 * p],     ah1, b[p].x, b[p].y);
            mma_bf16(acc[0][2 * p + 1], ah0, b[p].z, b[p].w);
            mma_bf16(acc[1][2 * p + 1], ah1, b[p].z, b[p].w);
            mma_bf16(acc[0][2 * p],     al0, b[p].x, b[p].y);
            mma_bf16(acc[1][2 * p],     al1, b[p].x, b[p].y);
            mma_bf16(acc[0][2 * p + 1], al0, b[p].z, b[p].w);
            mma_bf16(acc[1][2 * p + 1], al1, b[p].z, b[p].w);
        }
        #pragma unroll
        for (int p = 0; p < 4; p++) b[p] = sBl[(jp0 + p) * 32 + lid];
        #pragma unroll
        for (int p = 0; p < 4; p++) {
            mma_bf16(acc[0][2 * p],     ah0, b[p].x, b[p].y);
            mma_bf16(acc[1][2 * p],     ah1, b[p].x, b[p].y);
            mma_bf16(acc[0][2 * p + 1], ah0, b[p].z, b[p].w);
            mma_bf16(acc[1][2 * p + 1], ah1, b[p].z, b[p].w);
        }
    }
}

__device__ __forceinline__ void issue_B_prologue(char* smem, const __nv_bfloat16* wimg,
                                                 int tid) {
    load_B_slice(smem, wimg, 0, tid);
    load_B_slice(smem, wimg, 1, tid);
    load_B_slice(smem, wimg, 2, tid);
}

template<bool COMBINE>
__device__ __forceinline__ void convert_A(char* smem, const float* A, const float* B,
                                          float e, int row0, int M, int tid) {
    #pragma unroll
    for (int i = tid; i < 4096; i += 256) {
        int row = i >> 5;
        int k0  = (i & 31) * 4;
        int gr  = row0 + row;
        float4 v = make_float4(0.f, 0.f, 0.f, 0.f);
        if (gr < M) {
            v = *(const float4*)(A + (size_t)gr * HID + k0);
            if (COMBINE) {
                float4 b = *(const float4*)(B + (size_t)gr * HID + k0);
                v.x = fmaf(e, v.x, b.x); v.y = fmaf(e, v.y, b.y);
                v.z = fmaf(e, v.z, b.z); v.w = fmaf(e, v.w, b.w);
            }
        }
        write_afrag(smem, row, k0, v);
    }
}

__device__ __forceinline__ void zero_acc(float acc[2][8][4]) {
    #pragma unroll
    for (int mi = 0; mi < 2; mi++)
        #pragma unroll
        for (int nt = 0; nt < 8; nt++)
            #pragma unroll
            for (int c = 0; c < 4; c++) acc[mi][nt][c] = 0.f;
}

// Encode: out = relu(A @ W + bias)
__global__ __launch_bounds__(256, 2) void gemm_enc_kernel(
    const float* __restrict__ A,
    const __nv_bfloat16* __restrict__ wimg,
    const float* __restrict__ bias,
    float* __restrict__ out, int M)
{
    extern __shared__ char smem[];
    const int tid = threadIdx.x, w = tid >> 5, lid = tid & 31;
    const int row0 = blockIdx.x * 128;

    issue_B_prologue(smem, wimg, tid);
    if (tid < 128) *(float*)(smem + OFF_BIAS + tid * 4) = bias[tid];
    convert_A<false>(smem, A, nullptr, 0.f, row0, M, tid);

    float acc[2][8][4];
    zero_acc(acc);
    mma_pipe(smem, wimg, tid, w, lid, acc);

    const int g = lid >> 2, tq = lid & 3;
    const float* bs = (const float*)(smem + OFF_BIAS);
    #pragma unroll
    for (int mi = 0; mi < 2; mi++)
        #pragma unroll
        for (int nt = 0; nt < 8; nt++) {
            int col = (w >> 2) * 64 + nt * 8 + tq * 2;
            float b0 = bs[col], b1 = bs[col + 1];
            int r0 = row0 + (w & 3) * 32 + mi * 16 + g;
            if (r0 < M)
                *(float2*)(out + (size_t)r0 * HID + col) =
                    make_float2(fmaxf(acc[mi][nt][0] + b0, 0.f),
                                fmaxf(acc[mi][nt][1] + b1, 0.f));
            int r1 = r0 + 8;
            if (r1 < M)
                *(float2*)(out + (size_t)r1 * HID + col) =
                    make_float2(fmaxf(acc[mi][nt][2] + b0, 0.f),
                                fmaxf(acc[mi][nt][3] + b1, 0.f));
        }
}

// Fused 3-GEMM MLP: out = relu3(mlp((1+eps)*h + agg))
__global__ __launch_bounds__(256, 2) void mlp3_kernel(
    const float* __restrict__ A,
    const float* __restrict__ B,
    const float* __restrict__ eps,
    const __nv_bfloat16* __restrict__ wa,
    const __nv_bfloat16* __restrict__ wb,
    const __nv_bfloat16* __restrict__ wc,
    const float* __restrict__ ba,
    const float* __restrict__ bb,
    const float* __restrict__ bc,
    float* __restrict__ out, int M)
{
    extern __shared__ char smem[];
    const int tid = threadIdx.x, w = tid >> 5, lid = tid & 31;
    const int row0 = blockIdx.x * 128;
    const float e = 1.0f + eps[0];

    issue_B_prologue(smem, wa, tid);
    if (tid < 128) {
        *(float*)(smem + OFF_BIAS +        tid * 4) = ba[tid];
        *(float*)(smem + OFF_BIAS +  512 + tid * 4) = bb[tid];
        *(float*)(smem + OFF_BIAS + 1024 + tid * 4) = bc[tid];
    }
    convert_A<true>(smem, A, B, e, row0, M, tid);

    float acc[2][8][4];
    const int g = lid >> 2, tq = lid & 3;
    const __nv_bfloat16* ws[3] = {wa, wb, wc};

    #pragma unroll
    for (int st = 0; st < 3; st++) {
        zero_acc(acc);
        mma_pipe(smem, ws[st], tid, w, lid, acc);
        __syncthreads();

        const float* bs = (const float*)(smem + OFF_BIAS + st * 512);

        if (st < 2) {
            issue_B_prologue(smem, ws[st + 1], tid);
            uint4* dAh = (uint4*)(smem + OFF_AHI);
            uint4* dAl = (uint4*)(smem + OFF_ALO);
            #pragma unroll
            for (int mi = 0; mi < 2; mi++) {
                int mt = (w & 3) * 2 + mi;
                #pragma unroll
                for (int j = 0; j < 4; j++) {
                    int s = (w >> 2) * 4 + j;
                    int colA = (w >> 2) * 64 + (2 * j) * 8 + tq * 2;
                    int colB = colA + 8;
                    float bA0 = bs[colA], bA1 = bs[colA + 1];
                    float bB0 = bs[colB], bB1 = bs[colB + 1];
                    uint4 hi, lo;
                    pack_hilo(fmaxf(acc[mi][2 * j][0] + bA0, 0.f),
                              fmaxf(acc[mi][2 * j][1] + bA1, 0.f), hi.x, lo.x);
                    pack_hilo(fmaxf(acc[mi][2 * j][2] + bA0, 0.f),
                              fmaxf(acc[mi][2 * j][3] + bA1, 0.f), hi.y, lo.y);
                    pack_hilo(fmaxf(acc[mi][2 * j + 1][0] + bB0, 0.f),
                              fmaxf(acc[mi][2 * j + 1][1] + bB1, 0.f), hi.z, lo.z);
                    pack_hilo(fmaxf(acc[mi][2 * j + 1][2] + bB0, 0.f),
                              fmaxf(acc[mi][2 * j + 1][3] + bB1, 0.f), hi.w, lo.w);
                    int idx = (s * 8 + mt) * 32 + lid;
                    dAh[idx] = hi;
                    dAl[idx] = lo;
                }
            }
        } else {
            #pragma unroll
            for (int mi = 0; mi < 2; mi++)
                #pragma unroll
                for (int nt = 0; nt < 8; nt++) {
                    int col = (w >> 2) * 64 + nt * 8 + tq * 2;
                    float b0 = bs[col], b1 = bs[col + 1];
                    int r0 = row0 + (w & 3) * 32 + mi * 16 + g;
                    if (r0 < M)
                        *(float2*)(out + (size_t)r0 * HID + col) =
                            make_float2(fmaxf(acc[mi][nt][0] + b0, 0.f),
                                        fmaxf(acc[mi][nt][1] + b1, 0.f));
                    int r1 = r0 + 8;
                    if (r1 < M)
                        *(float2*)(out + (size_t)r1 * HID + col) =
                            make_float2(fmaxf(acc[mi][nt][2] + b0, 0.f),
                                        fmaxf(acc[mi][nt][3] + b1, 0.f));
                }
        }
    }
}

// ---------------------------------------------------------------------------
// Launch: CSR build forked onto a side stream, overlapped with prep+encode.
// ---------------------------------------------------------------------------
extern "C" void kernel_launch(void* const* d_in, const int* in_sizes, int n_in,
                              void* d_out, int out_size)
{
    const float* x    = (const float*)d_in[0];
    const int*   ei   = (const int*)  d_in[1];
    const int*   ea   = (const int*)  d_in[2];
    const float* Wx   = (const float*)d_in[3];
    const float* bx   = (const float*)d_in[4];
    const float* emb  = (const float*)d_in[5];
    const float* eps1 = (const float*)d_in[6];
    const float* eps2 = (const float*)d_in[7];
    const float* W1a  = (const float*)d_in[8];
    const float* b1a  = (const float*)d_in[9];
    const float* W1b  = (const float*)d_in[10];
    const float* b1b  = (const float*)d_in[11];
    const float* W1c  = (const float*)d_in[12];
    const float* b1c  = (const float*)d_in[13];
    const float* W2a  = (const float*)d_in[14];
    const float* b2a  = (const float*)d_in[15];
    const float* W2b  = (const float*)d_in[16];
    const float* b2b  = (const float*)d_in[17];
    const float* W2c  = (const float*)d_in[18];
    const float* b2c  = (const float*)d_in[19];

    const int M = in_sizes[0] / HID;   // 100000
    const int E = in_sizes[1] / 2;     // 1600000
    float* out = (float*)d_out;

    float* h    = nullptr; cudaGetSymbolAddress((void**)&h,    g_h);
    float* agg  = nullptr; cudaGetSymbolAddress((void**)&agg,  g_agg);
    __nv_bfloat16* wimg = nullptr; cudaGetSymbolAddress((void**)&wimg, g_wimg);
    int* deg    = nullptr; cudaGetSymbolAddress((void**)&deg,    g_deg);
    int* off    = nullptr; cudaGetSymbolAddress((void**)&off,    g_off);
    int* bsum   = nullptr; cudaGetSymbolAddress((void**)&bsum,   g_bsum);
    int* rank   = nullptr; cudaGetSymbolAddress((void**)&rank,   g_rank);
    int* packed = nullptr; cudaGetSymbolAddress((void**)&packed, g_packed);

    cudaFuncSetAttribute(gemm_enc_kernel,
                         cudaFuncAttributeMaxDynamicSharedMemorySize, SM_TOTAL);
    cudaFuncSetAttribute(mlp3_kernel,
                         cudaFuncAttributeMaxDynamicSharedMemorySize, SM_TOTAL);

    const int nb = (M + 2047) / 2048;
    const dim3 gemm_grid((M + 127) / 128);
    const dim3 agg_grid((M + 7) / 8);
    auto WI = [&](int i) { return wimg + (size_t)i * 32768; };

    // ---- fork: CSR build on side stream, prep+encode on main stream ----
    cudaEventRecord(g_ss.fork, 0);
    cudaStreamWaitEvent(g_ss.s, g_ss.fork, 0);

    // side stream: dst-sorted CSR build (hist emits ranks; fill atomic-free)
    cudaMemsetAsync(deg, 0, (size_t)M * sizeof(int), g_ss.s);
    hist_kernel<<<(E + 255) / 256, 256, 0, g_ss.s>>>(ei, deg, rank, E);
    scan1_kernel<<<nb, 512, 0, g_ss.s>>>(deg, off, bsum, M);
    scan3_kernel<<<nb, 512, 0, g_ss.s>>>(off, bsum, M, E);
    fill_kernel<<<(E + 255) / 256, 256, 0, g_ss.s>>>(ei, ea, off, rank, packed, E);
    cudaEventRecord(g_ss.join, g_ss.s);

    // main stream: weight prep + encode (independent of CSR)
    prep_all_kernel<<<dim3(64, 7), 256>>>(Wx, W1a, W1b, W1c, W2a, W2b, W2c, wimg);
    gemm_enc_kernel<<<gemm_grid, 256, SM_TOTAL>>>(x, WI(0), bx, h, M);

    // join before first aggregation (needs both h and CSR)
    cudaStreamWaitEvent(0, g_ss.join, 0);

    // GINE layer 1
    agg_kernel<<<agg_grid, 256>>>(h, packed, off, emb, agg, M);
    mlp3_kernel<<<gemm_grid, 256, SM_TOTAL>>>(h, agg, eps1, WI(1), WI(2), WI(3),
                                              b1a, b1b, b1c, h, M);

    // GINE layer 2
    agg_kernel<<<agg_grid, 256>>>(h, packed, off, emb, agg, M);
    mlp3_kernel<<<gemm_grid, 256, SM_TOTAL>>>(h, agg, eps2, WI(4), WI(5), WI(6),
                                              b2a, b2b, b2c, out, M);
}

// round 17
// speedup vs baseline: 1.0101x; 1.0101x over previous
#include <cuda_runtime.h>
#include <cuda_bf16.h>
#include <cstdint>

constexpr int HID = 128;
constexpr int N_NODES_MAX = 100000;
constexpr int N_EDGES_MAX = 1600000;
constexpr int N_EDGE_TYPES = 8;

// Scratch (device globals: allocation-free)
__device__ float g_h[(size_t)N_NODES_MAX * HID];
__device__ float g_agg[(size_t)N_NODES_MAX * HID];
__device__ __nv_bfloat16 g_wimg[7 * 2 * 16384];
// CSR scratch
__device__ int g_deg[N_NODES_MAX];          // histogram, then reused as cursor
__device__ int g_off[N_NODES_MAX + 1];
__device__ int g_bsum[256];
__device__ int g_packed[N_EDGES_MAX];       // src | (etype << 20)

// Side stream + fork/join events (host-side resources, static init)
struct SideStream {
    cudaStream_t s;
    cudaEvent_t fork, join;
    SideStream() {
        cudaStreamCreateWithFlags(&s, cudaStreamNonBlocking);
        cudaEventCreateWithFlags(&fork, cudaEventDisableTiming);
        cudaEventCreateWithFlags(&join, cudaEventDisableTiming);
    }
};
static SideStream g_ss;

// ---------------------------------------------------------------------------
// helpers
// ---------------------------------------------------------------------------
__device__ __forceinline__ uint32_t smem_u32(const void* p) {
    uint32_t a;
    asm("{ .reg .u64 t; cvta.to.shared.u64 t, %1; cvt.u32.u64 %0, t; }" : "=r"(a) : "l"(p));
    return a;
}
__device__ __forceinline__ void cp_async16(uint32_t saddr, const void* g) {
    asm volatile("cp.async.cg.shared.global [%0], [%1], 16;" :: "r"(saddr), "l"(g) : "memory");
}
__device__ __forceinline__ void cp_commit() {
    asm volatile("cp.async.commit_group;" ::: "memory");
}
template<int N>
__device__ __forceinline__ void cp_wait() {
    asm volatile("cp.async.wait_group %0;" :: "n"(N) : "memory");
}
__device__ __forceinline__ void mma_bf16(float* c, const uint4& a,
                                         uint32_t b0, uint32_t b1) {
    asm volatile(
        "mma.sync.aligned.m16n8k16.row.col.f32.bf16.bf16.f32 "
        "{%0,%1,%2,%3}, {%4,%5,%6,%7}, {%8,%9}, {%0,%1,%2,%3};"
        : "+f"(c[0]), "+f"(c[1]), "+f"(c[2]), "+f"(c[3])
        : "r"(a.x), "r"(a.y), "r"(a.z), "r"(a.w), "r"(b0), "r"(b1));
}
__device__ __forceinline__ void pack_hilo(float a, float b, uint32_t& hi, uint32_t& lo) {
    __nv_bfloat16 ha = __float2bfloat16_rn(a), hb = __float2bfloat16_rn(b);
    __nv_bfloat162 H(ha, hb);
    __nv_bfloat162 L(__float2bfloat16_rn(a - __bfloat162float(ha)),
                     __float2bfloat16_rn(b - __bfloat162float(hb)));
    hi = *(uint32_t*)&H;
    lo = *(uint32_t*)&L;
}

// smem layout (GEMM kernels): bias | A hi | A lo | B ring (4 x 8KB)
constexpr int OFF_BIAS = 0;                  // 2048 B
constexpr int OFF_AHI  = 2048;               // 32 KB
constexpr int OFF_ALO  = OFF_AHI + 32768;    // 32 KB
constexpr int OFF_B    = OFF_ALO + 32768;    // 4 x 8192
constexpr int SM_TOTAL = OFF_B + 4 * 8192;   // 100352 B -> 2 CTAs/SM

// frag address for element (row, k0) of the 128x128 A tile (k0 multiple of 4)
__device__ __forceinline__ uint32_t afrag_addr(int row, int k0) {
    int s    = k0 >> 4;
    int half = (k0 >> 3) & 1;
    int t    = (k0 >> 1) & 3;
    int g    = row & 7;
    int rbit = (row >> 3) & 1;
    int mt   = row >> 4;
    int r    = rbit + 2 * half;
    return (uint32_t)((s * 8 + mt) * 512 + (g * 4 + t) * 16 + r * 4);
}
__device__ __forceinline__ void write_afrag(char* smem, int row, int k0, float4 v) {
    uint32_t h01, l01, h23, l23;
    pack_hilo(v.x, v.y, h01, l01);
    pack_hilo(v.z, v.w, h23, l23);
    uint32_t base = afrag_addr(row, k0);
    *(uint32_t*)(smem + OFF_AHI + base)      = h01;
    *(uint32_t*)(smem + OFF_AHI + base + 16) = h23;
    *(uint32_t*)(smem + OFF_ALO + base)      = l01;
    *(uint32_t*)(smem + OFF_ALO + base + 16) = l23;
}

// issue one 8KB B slice (hi 4KB + lo 4KB) for k-step j into ring slot j&3
__device__ __forceinline__ void load_B_slice(char* smem, const __nv_bfloat16* wimg,
                                             int j, int tid) {
    uint32_t dst = smem_u32(smem + OFF_B + (j & 3) * 8192);
    const uint4* hs = (const uint4*)wimg + j * 256;
    const uint4* ls = (const uint4*)(wimg + 16384) + j * 256;
    cp_async16(dst + tid * 16,        hs + tid);
    cp_async16(dst + 4096 + tid * 16, ls + tid);
    cp_commit();
}

// ---------------------------------------------------------------------------
// Prep weights: split fp32 W into bf16 hi/lo in MMA B-fragment order
// ---------------------------------------------------------------------------
__global__ void prep_all_kernel(const float* W0, const float* W1, const float* W2,
                                const float* W3, const float* W4, const float* W5,
                                const float* W6, __nv_bfloat16* img) {
    const float* Ws[7] = {W0, W1, W2, W3, W4, W5, W6};
    int wi  = blockIdx.y;
    int idx = blockIdx.x * blockDim.x + threadIdx.x;
    if (idx >= 16384) return;
    int k = idx >> 7;
    int n = idx & 127;
    float w = Ws[wi][k * 128 + n];
    __nv_bfloat16 h = __float2bfloat16_rn(w);
    __nv_bfloat16 l = __float2bfloat16_rn(w - __bfloat162float(h));

    int s = k >> 4, half = (k & 15) >> 3, t = (k >> 1) & 3, e = k & 1;
    int g = n & 7, lane = g * 4 + t;
    int jt = n >> 3, jp = jt >> 1, which = jt & 1, reg = which * 2 + half;
    uint32_t off = (uint32_t)((s * 8 + jp) * 512 + lane * 16 + reg * 4 + e * 2);
    char* hi = (char*)(img + (size_t)wi * 32768);
    char* lo = hi + 32768;
    *(__nv_bfloat16*)(hi + off) = h;
    *(__nv_bfloat16*)(lo + off) = l;
}

// ---------------------------------------------------------------------------
// CSR build kernels (R12 configuration)
// ---------------------------------------------------------------------------
__global__ void hist_kernel(const int* __restrict__ ei, int* __restrict__ deg, int E) {
    int e = blockIdx.x * blockDim.x + threadIdx.x;
    if (e >= E) return;
    atomicAdd(&deg[ei[E + e]], 1);
}
__global__ __launch_bounds__(512) void scan1_kernel(
    const int* __restrict__ deg, int* __restrict__ out, int* __restrict__ bsum, int M)
{
    __shared__ int warp_sums[16];
    int tid = threadIdx.x;
    int base = blockIdx.x * 2048 + tid * 4;
    int v[4];
    #pragma unroll
    for (int j = 0; j < 4; j++) v[j] = (base + j < M) ? deg[base + j] : 0;
    int t = v[0] + v[1] + v[2] + v[3];
    int lane = tid & 31, wid = tid >> 5;
    int x = t;
    #pragma unroll
    for (int o = 1; o < 32; o <<= 1) {
        int y = __shfl_up_sync(0xFFFFFFFFu, x, o);
        if (lane >= o) x += y;
    }
    if (lane == 31) warp_sums[wid] = x;
    __syncthreads();
    if (wid == 0 && lane < 16) {
        int s = warp_sums[lane];
        #pragma unroll
        for (int o = 1; o < 16; o <<= 1) {
            int y = __shfl_up_sync(0xFFFFu, s, o);
            if (lane >= o) s += y;
        }
        warp_sums[lane] = s;
    }
    __syncthreads();
    int warp_excl = (wid == 0) ? 0 : warp_sums[wid - 1];
    int run = warp_excl + (x - t);
    #pragma unroll
    for (int j = 0; j < 4; j++) {
        if (base + j < M) out[base + j] = run;
        run += v[j];
    }
    if (tid == 0) bsum[blockIdx.x] = warp_sums[15];
}
__global__ __launch_bounds__(512) void scan3_kernel(
    int* __restrict__ off, int* __restrict__ cursor,
    const int* __restrict__ bsum, int M, int E)
{
    __shared__ int s_add;
    int tid = threadIdx.x;
    if (tid < 32) {
        int s = 0;
        int bid = (int)blockIdx.x;
        if (tid < bid)      s += bsum[tid];
        if (tid + 32 < bid) s += bsum[tid + 32];
        #pragma unroll
        for (int o = 16; o > 0; o >>= 1)
            s += __shfl_xor_sync(0xFFFFFFFFu, s, o);
        if (tid == 0) s_add = s;
    }
    __syncthreads();
    int base = blockIdx.x * 2048 + tid * 4;
    int add = s_add;
    #pragma unroll
    for (int j = 0; j < 4; j++) {
        if (base + j < M) {
            int v = off[base + j] + add;
            off[base + j] = v;
            cursor[base + j] = v;
        }
    }
    if (blockIdx.x == 0 && tid == 0) off[M] = E;
}
__global__ void fill_kernel(const int* __restrict__ ei, const int* __restrict__ et,
                            int* __restrict__ cursor, int* __restrict__ packed, int E)
{
    int e = blockIdx.x * blockDim.x + threadIdx.x;
    if (e >= E) return;
    int d = ei[E + e];
    int pos = atomicAdd(&cursor[d], 1);
    packed[pos] = ei[e] | (et[e] << 20);
}

// ---------------------------------------------------------------------------
// CSR aggregation (fp32, PDL): agg[n] = sum relu(h[src]+emb[et]); 8-edge unroll
// Prologue (trigger + smem emb staging) runs before griddepsync.
// ---------------------------------------------------------------------------
__global__ __launch_bounds__(256) void agg_kernel(
    const float* __restrict__ h, const int* __restrict__ packed,
    const int* __restrict__ off, const float* __restrict__ emb,
    float* __restrict__ agg, int M)
{
    cudaTriggerProgrammaticLaunchCompletion();

    __shared__ float semb[N_EDGE_TYPES * HID];
    for (int i = threadIdx.x; i < N_EDGE_TYPES * HID; i += 256) semb[i] = emb[i];
    __syncthreads();

    cudaGridDependencySynchronize();   // h (and CSR) ready

    int n = blockIdx.x * 8 + (threadIdx.x >> 5);
    if (n >= M) return;
    int lane = threadIdx.x & 31;
    const int k0 = lane * 4;

    int beg = off[n], end = off[n + 1];
    float4 acc = make_float4(0.f, 0.f, 0.f, 0.f);
    int e = beg;
    for (; e + 8 <= end; e += 8) {
        int p[8];
        #pragma unroll
        for (int u = 0; u < 8; u++) p[u] = __ldg(packed + e + u);
        float4 hv[8];
        #pragma unroll
        for (int u = 0; u < 8; u++)
            hv[u] = *(const float4*)(h + (size_t)(p[u] & 0xFFFFF) * HID + k0);
        #pragma unroll
        for (int u = 0; u < 8; u++) {
            const float4 ev = *(const float4*)(semb + (p[u] >> 20) * HID + k0);
            acc.x += fmaxf(hv[u].x + ev.x, 0.f);
            acc.y += fmaxf(hv[u].y + ev.y, 0.f);
            acc.z += fmaxf(hv[u].z + ev.z, 0.f);
            acc.w += fmaxf(hv[u].w + ev.w, 0.f);
        }
    }
    for (; e < end; e++) {
        int p0 = __ldg(packed + e);
        float4 h0 = *(const float4*)(h + (size_t)(p0 & 0xFFFFF) * HID + k0);
        const float4 e0 = *(const float4*)(semb + (p0 >> 20) * HID + k0);
        acc.x += fmaxf(h0.x + e0.x, 0.f);
        acc.y += fmaxf(h0.y + e0.y, 0.f);
        acc.z += fmaxf(h0.z + e0.z, 0.f);
        acc.w += fmaxf(h0.w + e0.w, 0.f);
    }
    *(float4*)(agg + (size_t)n * HID + k0) = acc;
}

// ---------------------------------------------------------------------------
// Pipelined GEMM mainloop: B slices streamed via 4-slot cp.async ring.
// PRECONDITION: slices 0,1,2 of wimg already issued by all threads.
// ---------------------------------------------------------------------------
__device__ __forceinline__ void mma_pipe(char* smem, const __nv_bfloat16* wimg,
                                         int tid, int w, int lid,
                                         float acc[2][8][4]) {
    const int mt0 = (w & 3) * 2;
    const int jp0 = (w >> 2) * 4;
    const uint4* sAh = (const uint4*)(smem + OFF_AHI);
    const uint4* sAl = (const uint4*)(smem + OFF_ALO);
    #pragma unroll
    for (int s = 0; s < 8; s++) {
        if (s < 6)      cp_wait<2>();
        else if (s == 6) cp_wait<1>();
        else            cp_wait<0>();
        __syncthreads();
        if (s + 3 < 8) load_B_slice(smem, wimg, s + 3, tid);

        const uint4* sBh = (const uint4*)(smem + OFF_B + (s & 3) * 8192);
        const uint4* sBl = (const uint4*)(smem + OFF_B + (s & 3) * 8192 + 4096);

        uint4 ah0 = sAh[(s * 8 + mt0) * 32 + lid];
        uint4 ah1 = sAh[(s * 8 + mt0 + 1) * 32 + lid];
        uint4 al0 = sAl[(s * 8 + mt0) * 32 + lid];
        uint4 al1 = sAl[(s * 8 + mt0 + 1) * 32 + lid];
        uint4 b[4];
        #pragma unroll
        for (int p = 0; p < 4; p++) b[p] = sBh[(jp0 + p) * 32 + lid];
        #pragma unroll
        for (int p = 0; p < 4; p++) {
            mma_bf16(acc[0][2 * p],     ah0, b[p].x, b[p].y);
            mma_bf16(acc[1][2 * p],     ah1, b[p].x, b[p].y);
            mma_bf16(acc[0][2 * p + 1], ah0, b[p].z, b[p].w);
            mma_bf16(acc[1][2 * p + 1], ah1, b[p].z, b[p].w);
            mma_bf16(acc[0][2 * p],     al0, b[p].x, b[p].y);
            mma_bf16(acc[1][2 * p],     al1, b[p].x, b[p].y);
            mma_bf16(acc[0][2 * p + 1], al0, b[p].z, b[p].w);
            mma_bf16(acc[1][2 * p + 1], al1, b[p].z, b[p].w);
        }
        #pragma unroll
        for (int p = 0; p < 4; p++) b[p] = sBl[(jp0 + p) * 32 + lid];
        #pragma unroll
        for (int p = 0; p < 4; p++) {
            mma_bf16(acc[0][2 * p],     ah0, b[p].x, b[p].y);
            mma_bf16(acc[1][2 * p],     ah1, b[p].x, b[p].y);
            mma_bf16(acc[0][2 * p + 1], ah0, b[p].z, b[p].w);
            mma_bf16(acc[1][2 * p + 1], ah1, b[p].z, b[p].w);
        }
    }
}

__device__ __forceinline__ void issue_B_prologue(char* smem, const __nv_bfloat16* wimg,
                                                 int tid) {
    load_B_slice(smem, wimg, 0, tid);
    load_B_slice(smem, wimg, 1, tid);
    load_B_slice(smem, wimg, 2, tid);
}

template<bool COMBINE>
__device__ __forceinline__ void convert_A(char* smem, const float* A, const float* B,
                                          float e, int row0, int M, int tid) {
    #pragma unroll
    for (int i = tid; i < 4096; i += 256) {
        int row = i >> 5;
        int k0  = (i & 31) * 4;
        int gr  = row0 + row;
        float4 v = make_float4(0.f, 0.f, 0.f, 0.f);
        if (gr < M) {
            v = *(const float4*)(A + (size_t)gr * HID + k0);
            if (COMBINE) {
                float4 b = *(const float4*)(B + (size_t)gr * HID + k0);
                v.x = fmaf(e, v.x, b.x); v.y = fmaf(e, v.y, b.y);
                v.z = fmaf(e, v.z, b.z); v.w = fmaf(e, v.w, b.w);
            }
        }
        write_afrag(smem, row, k0, v);
    }
}

__device__ __forceinline__ void zero_acc(float acc[2][8][4]) {
    #pragma unroll
    for (int mi = 0; mi < 2; mi++)
        #pragma unroll
        for (int nt = 0; nt < 8; nt++)
            #pragma unroll
            for (int c = 0; c < 4; c++) acc[mi][nt][c] = 0.f;
}

// Encode: out = relu(A @ W + bias)
__global__ __launch_bounds__(256, 2) void gemm_enc_kernel(
    const float* __restrict__ A,
    const __nv_bfloat16* __restrict__ wimg,
    const float* __restrict__ bias,
    float* __restrict__ out, int M)
{
    cudaTriggerProgrammaticLaunchCompletion();

    extern __shared__ char smem[];
    const int tid = threadIdx.x, w = tid >> 5, lid = tid & 31;
    const int row0 = blockIdx.x * 128;

    issue_B_prologue(smem, wimg, tid);
    if (tid < 128) *(float*)(smem + OFF_BIAS + tid * 4) = bias[tid];
    convert_A<false>(smem, A, nullptr, 0.f, row0, M, tid);

    float acc[2][8][4];
    zero_acc(acc);
    mma_pipe(smem, wimg, tid, w, lid, acc);

    const int g = lid >> 2, tq = lid & 3;
    const float* bs = (const float*)(smem + OFF_BIAS);
    #pragma unroll
    for (int mi = 0; mi < 2; mi++)
        #pragma unroll
        for (int nt = 0; nt < 8; nt++) {
            int col = (w >> 2) * 64 + nt * 8 + tq * 2;
            float b0 = bs[col], b1 = bs[col + 1];
            int r0 = row0 + (w & 3) * 32 + mi * 16 + g;
            if (r0 < M)
                *(float2*)(out + (size_t)r0 * HID + col) =
                    make_float2(fmaxf(acc[mi][nt][0] + b0, 0.f),
                                fmaxf(acc[mi][nt][1] + b1, 0.f));
            int r1 = r0 + 8;
            if (r1 < M)
                *(float2*)(out + (size_t)r1 * HID + col) =
                    make_float2(fmaxf(acc[mi][nt][2] + b0, 0.f),
                                fmaxf(acc[mi][nt][3] + b1, 0.f));
        }
}

// Fused 3-GEMM MLP (PDL): out = relu3(mlp((1+eps)*h + agg))
// Prologue (trigger + B-ring prefetch + bias) runs before griddepsync.
__global__ __launch_bounds__(256, 2) void mlp3_kernel(
    const float* __restrict__ A,
    const float* __restrict__ B,
    const float* __restrict__ eps,
    const __nv_bfloat16* __restrict__ wa,
    const __nv_bfloat16* __restrict__ wb,
    const __nv_bfloat16* __restrict__ wc,
    const float* __restrict__ ba,
    const float* __restrict__ bb,
    const float* __restrict__ bc,
    float* __restrict__ out, int M)
{
    cudaTriggerProgrammaticLaunchCompletion();

    extern __shared__ char smem[];
    const int tid = threadIdx.x, w = tid >> 5, lid = tid & 31;
    const int row0 = blockIdx.x * 128;

    issue_B_prologue(smem, wa, tid);   // wimg written long ago: safe pre-sync
    if (tid < 128) {
        *(float*)(smem + OFF_BIAS +        tid * 4) = ba[tid];
        *(float*)(smem + OFF_BIAS +  512 + tid * 4) = bb[tid];
        *(float*)(smem + OFF_BIAS + 1024 + tid * 4) = bc[tid];
    }

    cudaGridDependencySynchronize();   // agg (immediate predecessor) ready

    const float e = 1.0f + eps[0];
    convert_A<true>(smem, A, B, e, row0, M, tid);

    float acc[2][8][4];
    const int g = lid >> 2, tq = lid & 3;
    const __nv_bfloat16* ws[3] = {wa, wb, wc};

    #pragma unroll
    for (int st = 0; st < 3; st++) {
        zero_acc(acc);
        mma_pipe(smem, ws[st], tid, w, lid, acc);
        __syncthreads();

        const float* bs = (const float*)(smem + OFF_BIAS + st * 512);

        if (st < 2) {
            issue_B_prologue(smem, ws[st + 1], tid);
            uint4* dAh = (uint4*)(smem + OFF_AHI);
            uint4* dAl = (uint4*)(smem + OFF_ALO);
            #pragma unroll
            for (int mi = 0; mi < 2; mi++) {
                int mt = (w & 3) * 2 + mi;
                #pragma unroll
                for (int j = 0; j < 4; j++) {
                    int s = (w >> 2) * 4 + j;
                    int colA = (w >> 2) * 64 + (2 * j) * 8 + tq * 2;
                    int colB = colA + 8;
                    float bA0 = bs[colA], bA1 = bs[colA + 1];
                    float bB0 = bs[colB], bB1 = bs[colB + 1];
                    uint4 hi, lo;
                    pack_hilo(fmaxf(acc[mi][2 * j][0] + bA0, 0.f),
                              fmaxf(acc[mi][2 * j][1] + bA1, 0.f), hi.x, lo.x);
                    pack_hilo(fmaxf(acc[mi][2 * j][2] + bA0, 0.f),
                              fmaxf(acc[mi][2 * j][3] + bA1, 0.f), hi.y, lo.y);
                    pack_hilo(fmaxf(acc[mi][2 * j + 1][0] + bB0, 0.f),
                              fmaxf(acc[mi][2 * j + 1][1] + bB1, 0.f), hi.z, lo.z);
                    pack_hilo(fmaxf(acc[mi][2 * j + 1][2] + bB0, 0.f),
                              fmaxf(acc[mi][2 * j + 1][3] + bB1, 0.f), hi.w, lo.w);
                    int idx = (s * 8 + mt) * 32 + lid;
                    dAh[idx] = hi;
                    dAl[idx] = lo;
                }
            }
        } else {
            #pragma unroll
            for (int mi = 0; mi < 2; mi++)
                #pragma unroll
                for (int nt = 0; nt < 8; nt++) {
                    int col = (w >> 2) * 64 + nt * 8 + tq * 2;
                    float b0 = bs[col], b1 = bs[col + 1];
                    int r0 = row0 + (w & 3) * 32 + mi * 16 + g;
                    if (r0 < M)
                        *(float2*)(out + (size_t)r0 * HID + col) =
                            make_float2(fmaxf(acc[mi][nt][0] + b0, 0.f),
                                        fmaxf(acc[mi][nt][1] + b1, 0.f));
                    int r1 = r0 + 8;
                    if (r1 < M)
                        *(float2*)(out + (size_t)r1 * HID + col) =
                            make_float2(fmaxf(acc[mi][nt][2] + b0, 0.f),
                                        fmaxf(acc[mi][nt][3] + b1, 0.f));
                }
        }
    }
}

// ---------------------------------------------------------------------------
// Launch: CSR build on side stream; main-stream chain uses PDL.
// ---------------------------------------------------------------------------
template<typename... Args>
static void launch_pdl(void (*kern)(Args...), dim3 grid, dim3 block, size_t shm,
                       cudaStream_t stream, Args... args)
{
    cudaLaunchConfig_t cfg = {};
    cfg.gridDim = grid;
    cfg.blockDim = block;
    cfg.dynamicSmemBytes = shm;
    cfg.stream = stream;
    cudaLaunchAttribute attr[1];
    attr[0].id = cudaLaunchAttributeProgrammaticStreamSerialization;
    attr[0].val.programmaticStreamSerializationAllowed = 1;
    cfg.attrs = attr;
    cfg.numAttrs = 1;
    cudaLaunchKernelEx(&cfg, kern, args...);
}

extern "C" void kernel_launch(void* const* d_in, const int* in_sizes, int n_in,
                              void* d_out, int out_size)
{
    const float* x    = (const float*)d_in[0];
    const int*   ei   = (const int*)  d_in[1];
    const int*   ea   = (const int*)  d_in[2];
    const float* Wx   = (const float*)d_in[3];
    const float* bx   = (const float*)d_in[4];
    const float* emb  = (const float*)d_in[5];
    const float* eps1 = (const float*)d_in[6];
    const float* eps2 = (const float*)d_in[7];
    const float* W1a  = (const float*)d_in[8];
    const float* b1a  = (const float*)d_in[9];
    const float* W1b  = (const float*)d_in[10];
    const float* b1b  = (const float*)d_in[11];
    const float* W1c  = (const float*)d_in[12];
    const float* b1c  = (const float*)d_in[13];
    const float* W2a  = (const float*)d_in[14];
    const float* b2a  = (const float*)d_in[15];
    const float* W2b  = (const float*)d_in[16];
    const float* b2b  = (const float*)d_in[17];
    const float* W2c  = (const float*)d_in[18];
    const float* b2c  = (const float*)d_in[19];

    const int M = in_sizes[0] / HID;   // 100000
    const int E = in_sizes[1] / 2;     // 1600000
    float* out = (float*)d_out;

    float* h    = nullptr; cudaGetSymbolAddress((void**)&h,    g_h);
    float* agg  = nullptr; cudaGetSymbolAddress((void**)&agg,  g_agg);
    __nv_bfloat16* wimg = nullptr; cudaGetSymbolAddress((void**)&wimg, g_wimg);
    int* deg    = nullptr; cudaGetSymbolAddress((void**)&deg,    g_deg);
    int* off    = nullptr; cudaGetSymbolAddress((void**)&off,    g_off);
    int* bsum   = nullptr; cudaGetSymbolAddress((void**)&bsum,   g_bsum);
    int* packed = nullptr; cudaGetSymbolAddress((void**)&packed, g_packed);

    cudaFuncSetAttribute(gemm_enc_kernel,
                         cudaFuncAttributeMaxDynamicSharedMemorySize, SM_TOTAL);
    cudaFuncSetAttribute(mlp3_kernel,
                         cudaFuncAttributeMaxDynamicSharedMemorySize, SM_TOTAL);

    const int nb = (M + 2047) / 2048;
    const dim3 gemm_grid((M + 127) / 128);
    const dim3 agg_grid((M + 7) / 8);
    auto WI = [&](int i) { return wimg + (size_t)i * 32768; };

    // ---- fork: CSR build on side stream, prep+encode on main stream ----
    cudaEventRecord(g_ss.fork, 0);
    cudaStreamWaitEvent(g_ss.s, g_ss.fork, 0);

    cudaMemsetAsync(deg, 0, (size_t)M * sizeof(int), g_ss.s);
    hist_kernel<<<(E + 255) / 256, 256, 0, g_ss.s>>>(ei, deg, E);
    scan1_kernel<<<nb, 512, 0, g_ss.s>>>(deg, off, bsum, M);
    scan3_kernel<<<nb, 512, 0, g_ss.s>>>(off, deg, bsum, M, E);
    fill_kernel<<<(E + 255) / 256, 256, 0, g_ss.s>>>(ei, ea, deg, packed, E);
    cudaEventRecord(g_ss.join, g_ss.s);

    // main stream: weight prep + encode
    prep_all_kernel<<<dim3(64, 7), 256>>>(Wx, W1a, W1b, W1c, W2a, W2b, W2c, wimg);
    gemm_enc_kernel<<<gemm_grid, 256, SM_TOTAL>>>(x, WI(0), bx, h, M);

    cudaStreamWaitEvent(0, g_ss.join, 0);   // join: need CSR + h

    // GINE layer 1 (PDL chain: agg <- enc, mlp3 <- agg)
    launch_pdl(agg_kernel, agg_grid, dim3(256), 0, (cudaStream_t)0,
               (const float*)h, (const int*)packed, (const int*)off,
               (const float*)emb, (float*)agg, (int)M);
    launch_pdl(mlp3_kernel, gemm_grid, dim3(256), (size_t)SM_TOTAL, (cudaStream_t)0,
               (const float*)h, (const float*)agg, (const float*)eps1,
               (const __nv_bfloat16*)WI(1), (const __nv_bfloat16*)WI(2),
               (const __nv_bfloat16*)WI(3),
               (const float*)b1a, (const float*)b1b, (const float*)b1c,
               (float*)h, (int)M);

    // GINE layer 2
    launch_pdl(agg_kernel, agg_grid, dim3(256), 0, (cudaStream_t)0,
               (const float*)h, (const int*)packed, (const int*)off,
               (const float*)emb, (float*)agg, (int)M);
    launch_pdl(mlp3_kernel, gemm_grid, dim3(256), (size_t)SM_TOTAL, (cudaStream_t)0,
               (const float*)h, (const float*)agg, (const float*)eps2,
               (const __nv_bfloat16*)WI(4), (const __nv_bfloat16*)WI(5),
               (const __nv_bfloat16*)WI(6),
               (const float*)b2a, (const float*)b2b, (const float*)b2c,
               (float*)out, (int)M);
}